// round 14
// baseline (speedup 1.0000x reference)
#include <cuda_runtime.h>

// ---------------- problem constants ----------------
#define N_NODES 100000
#define NE      1600000
#define NE3     4800000

// per-node precomputed A = Wfc1[:, :128] @ mvc_norm, B = Wfc1[:, 128:] @ mvc_norm + b_fc1
__device__ __align__(16) float g_A[(size_t)N_NODES * 64];
__device__ __align__(16) float g_B[(size_t)N_NODES * 64];

#define BN  32      // nodes per block (100000 = 3125 * 32, exact)
#define TPB 256

// ---- shared memory layout (floats) ----
// xs : [256][40] X tile (k-major); overwritten by h tile [c][40] after GEMM1
// mvs: [128][36] mvc tile
// ws : weight staging; GEMM1: [256 rows][21] (KC=16); GEMM2/3: [128 rows][37] (KC=32)
constexpr int XS_STRIDE = 40;
constexpr int XS_OFF  = 0;
constexpr int XS_SZ   = 256 * XS_STRIDE;     // 10240
constexpr int MV_OFF  = XS_OFF + XS_SZ;
constexpr int MV_SZ   = 128 * 36;            // 4608
constexpr int WS_OFF  = MV_OFF + MV_SZ;
constexpr int WS_SZ   = 256 * 21;            // 5376 (>= 128*37 = 4736)
constexpr int RED_OFF = WS_OFF + WS_SZ;
constexpr int RED_SZ  = 8 * 32 + 32;         // 288
constexpr int SMEM_FLOATS = RED_OFF + RED_SZ;
constexpr int SMEM_BYTES  = SMEM_FLOATS * 4; // 82048 B -> 2 blocks/SM

// ---------------- packed fp32x2 helpers (sm_103a) ----------------
__device__ __forceinline__ unsigned long long pack2(float v) {
    unsigned long long r;
    asm("mov.b64 %0, {%1, %1};" : "=l"(r) : "f"(v));
    return r;
}
__device__ __forceinline__ void ffma2(unsigned long long& d,
                                      unsigned long long a,
                                      unsigned long long b) {
    asm("fma.rn.f32x2 %0, %1, %2, %0;" : "+l"(d) : "l"(a), "l"(b));
}
__device__ __forceinline__ float2 unpack2(unsigned long long v) {
    float2 f;
    asm("mov.b64 {%0, %1}, %2;" : "=f"(f.x), "=f"(f.y) : "l"(v));
    return f;
}

// ---------------- exact 3-way tf32 split ----------------
// x = hi + mid + lo EXACTLY (11+11+2 bits cover fp32's 24).
// All tf32*tf32 products are exact in the fp32 accumulator; the only
// dropped terms (mid*lo, lo*mid, lo*lo) are <= 2^-33 relative.
__device__ __forceinline__ void split3(float x, unsigned& h, unsigned& m, unsigned& l) {
    unsigned hb, mb, lb;
    asm("cvt.rna.tf32.f32 %0, %1;" : "=r"(hb) : "f"(x));
    float r1 = x - __uint_as_float(hb);
    asm("cvt.rna.tf32.f32 %0, %1;" : "=r"(mb) : "f"(r1));
    float r2 = r1 - __uint_as_float(mb);
    asm("cvt.rna.tf32.f32 %0, %1;" : "=r"(lb) : "f"(r2));
    h = hb; m = mb; l = lb;
}

// mma.m16n8k8 tf32: D += A * B (fp32 accumulate)
__device__ __forceinline__ void mma8(float* d, const unsigned* a, const unsigned* b) {
    asm("mma.sync.aligned.m16n8k8.row.col.f32.tf32.tf32.f32 "
        "{%0,%1,%2,%3}, {%4,%5,%6,%7}, {%8,%9}, {%0,%1,%2,%3};"
        : "+f"(d[0]), "+f"(d[1]), "+f"(d[2]), "+f"(d[3])
        : "r"(a[0]), "r"(a[1]), "r"(a[2]), "r"(a[3]), "r"(b[0]), "r"(b[1]));
}

// =====================================================================
// Node kernel: 32-node tile, 256 threads, 2 blocks/SM.
// GEMM1 on tensor cores (tf32 3-way split, 6 products). GEMM2/3 scalar
// f32x2 (unchanged R12 math). Register-prefetch weight staging.
// =====================================================================
__global__ void __launch_bounds__(TPB, 2) node_kernel(
    const float* __restrict__ trace,   // (2, N, 128)
    const float* __restrict__ Wlin,    // (256, 256)
    const float* __restrict__ Wlin2,   // (128, 256)
    const float* __restrict__ Wfc1,    // (64, 256)
    const float* __restrict__ bfc1)    // (64,)
{
    extern __shared__ float sm[];
    float* xs  = sm + XS_OFF;    // [k][40] X; later h [c][40]
    float* mvs = sm + MV_OFF;    // [c][36]
    float* ws  = sm + WS_OFF;    // staging
    float* red = sm + RED_OFF;   // [8][32]
    float* nrm = red + 256;      // [32]

    const int t    = threadIdx.x;
    const int lane = t & 31;
    const int w    = t >> 5;     // 0..7
    const int qid  = lane >> 2;  // 0..7
    const int tig  = lane & 3;   // 0..3
    const int n0   = blockIdx.x * BN;

    // ---- issue X tile loads into registers (coalesced along k) ----
    float xv[32];
    #pragma unroll
    for (int i = 0; i < 4; i++) {
        int nl = w * 4 + i;
        int n  = n0 + nl;
        #pragma unroll
        for (int j = 0; j < 8; j++) {
            int k = lane + 32 * j;
            xv[i * 8 + j] = (k < 128)
                ? trace[(size_t)n * 128 + k]
                : trace[(size_t)(N_NODES + n) * 128 + (k - 128)];
        }
    }
    // ---- prefetch GEMM1 weight chunk 0 (KC=16, 16/thread) ----
    float wr[16];
    #pragma unroll
    for (int r = 0; r < 16; r++) {
        int idx = r * 256 + t;
        wr[r] = Wlin[(idx >> 4) * 256 + (idx & 15)];
    }
    // ---- store X tile to smem (k-major, stride 40) ----
    #pragma unroll
    for (int i = 0; i < 4; i++) {
        int nl = w * 4 + i;
        #pragma unroll
        for (int j = 0; j < 8; j++) {
            int k = lane + 32 * j;
            xs[k * XS_STRIDE + nl] = xv[i * 8 + j];
        }
    }

    // ================= GEMM1 (tensor): h = relu(Wlin @ x) =================
    // M = 256 cols (warp w owns m-tiles 2w, 2w+1), N = 32 nodes (4 n8-tiles),
    // K = 256 (16 chunks of 16, 2 k8-steps each).
    float dacc[2][4][4];
    #pragma unroll
    for (int a = 0; a < 2; a++)
        #pragma unroll
        for (int b = 0; b < 4; b++)
            #pragma unroll
            for (int cc = 0; cc < 4; cc++) dacc[a][b][cc] = 0.0f;

    for (int c = 0; c < 16; c++) {
        // publish chunk c: ws[row][21], row = weight output-col, 16 kk
        #pragma unroll
        for (int r = 0; r < 16; r++) {
            int idx = r * 256 + t;
            ws[(idx >> 4) * 21 + (idx & 15)] = wr[r];
        }
        __syncthreads();   // c==0: also publishes X tile
        if (c < 15) {
            #pragma unroll
            for (int r = 0; r < 16; r++) {
                int idx = r * 256 + t;
                wr[r] = Wlin[(idx >> 4) * 256 + (c + 1) * 16 + (idx & 15)];
            }
        }
        #pragma unroll
        for (int k8 = 0; k8 < 2; k8++) {
            const int kb = k8 * 8;
            const int kg = c * 16 + kb;
            // A fragments (weights), 2 m-tiles, split hi/mid/lo
            unsigned Ah[2][4], Am[2][4], Al[2][4];
            #pragma unroll
            for (int mt = 0; mt < 2; mt++) {
                int cb = 32 * w + 16 * mt;
                float a0 = ws[(cb + qid)     * 21 + kb + tig];
                float a1 = ws[(cb + 8 + qid) * 21 + kb + tig];
                float a2 = ws[(cb + qid)     * 21 + kb + tig + 4];
                float a3 = ws[(cb + 8 + qid) * 21 + kb + tig + 4];
                split3(a0, Ah[mt][0], Am[mt][0], Al[mt][0]);
                split3(a1, Ah[mt][1], Am[mt][1], Al[mt][1]);
                split3(a2, Ah[mt][2], Am[mt][2], Al[mt][2]);
                split3(a3, Ah[mt][3], Am[mt][3], Al[mt][3]);
            }
            // B fragments (X), 4 n-tiles
            #pragma unroll
            for (int nt = 0; nt < 4; nt++) {
                int n = nt * 8 + qid;
                float b0 = xs[(kg + tig)     * XS_STRIDE + n];
                float b1 = xs[(kg + tig + 4) * XS_STRIDE + n];
                unsigned Bh[2], Bm[2], Bl[2];
                split3(b0, Bh[0], Bm[0], Bl[0]);
                split3(b1, Bh[1], Bm[1], Bl[1]);
                #pragma unroll
                for (int mt = 0; mt < 2; mt++) {
                    float* D = dacc[mt][nt];
                    mma8(D, Ah[mt], Bh);   // hi*hi
                    mma8(D, Ah[mt], Bm);   // hi*mid
                    mma8(D, Am[mt], Bh);   // mid*hi
                    mma8(D, Am[mt], Bm);   // mid*mid
                    mma8(D, Ah[mt], Bl);   // hi*lo
                    mma8(D, Al[mt], Bh);   // lo*hi
                }
            }
        }
        __syncthreads();
    }

    // ---- prefetch GEMM2 chunk 0 (KC=32, 16/thread) ----
    #pragma unroll
    for (int r = 0; r < 16; r++) {
        int idx = r * 256 + t;
        wr[r] = Wlin2[(idx >> 5) * 256 + (idx & 31)];
    }

    // ---- store h = relu(D) into xs region [c][40] ----
    #pragma unroll
    for (int mt = 0; mt < 2; mt++) {
        int cb = 32 * w + 16 * mt;
        #pragma unroll
        for (int nt = 0; nt < 4; nt++) {
            float* D = dacc[mt][nt];
            int ncol = nt * 8 + 2 * tig;
            float2 v0 = make_float2(fmaxf(D[0], 0.f), fmaxf(D[1], 0.f));
            float2 v1 = make_float2(fmaxf(D[2], 0.f), fmaxf(D[3], 0.f));
            *(float2*)(xs + (cb + qid)     * XS_STRIDE + ncol) = v0;
            *(float2*)(xs + (cb + 8 + qid) * XS_STRIDE + ncol) = v1;
        }
    }

    // ================= GEMM2 (scalar f32x2): mvc = Wlin2 @ h =================
    const int d0 = t & 63;
    const int on = (t >> 6) * 8;
    {
        unsigned long long c0a[4], c1a[4];
        #pragma unroll
        for (int i = 0; i < 4; i++) { c0a[i] = 0ull; c1a[i] = 0ull; }

        for (int c = 0; c < 8; c++) {
            #pragma unroll
            for (int r = 0; r < 16; r++) {
                int idx = r * 256 + t;
                ws[(idx >> 5) * 37 + (idx & 31)] = wr[r];
            }
            __syncthreads();   // c==0: also publishes h stores
            if (c < 7) {
                #pragma unroll
                for (int r = 0; r < 16; r++) {
                    int idx = r * 256 + t;
                    wr[r] = Wlin2[(idx >> 5) * 256 + (c + 1) * 32 + (idx & 31)];
                }
            }
            #pragma unroll
            for (int kk = 0; kk < 32; kk++) {
                unsigned long long wv0 = pack2(ws[d0 * 37 + kk]);
                unsigned long long wv1 = pack2(ws[(d0 + 64) * 37 + kk]);
                const ulonglong2* hr =
                    (const ulonglong2*)(xs + (c * 32 + kk) * XS_STRIDE + on);
                #pragma unroll
                for (int q = 0; q < 2; q++) {
                    ulonglong2 h2 = hr[q];
                    ffma2(c0a[2*q],   wv0, h2.x);
                    ffma2(c0a[2*q+1], wv0, h2.y);
                    ffma2(c1a[2*q],   wv1, h2.x);
                    ffma2(c1a[2*q+1], wv1, h2.y);
                }
            }
            __syncthreads();
        }
        // store mvc (disjoint region)
        float4* m0 = (float4*)(mvs + d0 * 36 + on);
        float4* m1 = (float4*)(mvs + (d0 + 64) * 36 + on);
        #pragma unroll
        for (int q = 0; q < 2; q++) {
            float2 p = unpack2(c0a[2*q]), r2 = unpack2(c0a[2*q+1]);
            m0[q] = make_float4(p.x, p.y, r2.x, r2.y);
            p = unpack2(c1a[2*q]); r2 = unpack2(c1a[2*q+1]);
            m1[q] = make_float4(p.x, p.y, r2.x, r2.y);
        }
    }
    __syncthreads();   // mvs stores visible

    // ---- prefetch GEMM3 chunk 0 (combined [A;B] rows, KC=32) ----
    #pragma unroll
    for (int r = 0; r < 16; r++) {
        int idx = r * 256 + t;
        int j = idx >> 5, kk = idx & 31;
        wr[r] = (j < 64) ? Wfc1[j * 256 + kk]
                         : Wfc1[(j - 64) * 256 + 128 + kk];
    }
    const float bias = __ldg(&bfc1[t & 63]);

    // ---------------- row norm + normalize ----------------
    {
        int n = t & 31, p = t >> 5;   // 8 groups x 16 cols
        float s = 0.0f;
        #pragma unroll 4
        for (int cc = p * 16; cc < p * 16 + 16; cc++) {
            float v = mvs[cc * 36 + n];
            s += v * v;
        }
        red[p * 32 + n] = s;
        __syncthreads();
        if (t < 32) {
            float ss = 0.0f;
            #pragma unroll
            for (int p2 = 0; p2 < 8; p2++) ss += red[p2 * 32 + t];
            nrm[t] = fmaxf(sqrtf(ss), 1e-12f);
        }
        __syncthreads();
        #pragma unroll
        for (int i = 0; i < 16; i++) {
            int idx = i * TPB + t;
            int cc = idx >> 5, n2 = idx & 31;
            mvs[cc * 36 + n2] = mvs[cc * 36 + n2] / nrm[n2];
        }
    }

    // ================= GEMM3 (scalar f32x2): A/B = Wfc1-split @ mvc_norm =================
    {
        const int j0 = t & 63;
        unsigned long long aA[4], aB[4];
        #pragma unroll
        for (int i = 0; i < 4; i++) { aA[i] = 0ull; aB[i] = 0ull; }

        for (int c = 0; c < 4; c++) {
            #pragma unroll
            for (int r = 0; r < 16; r++) {
                int idx = r * 256 + t;
                ws[(idx >> 5) * 37 + (idx & 31)] = wr[r];
            }
            __syncthreads();   // c==0: also publishes normalized mvs
            if (c < 3) {
                #pragma unroll
                for (int r = 0; r < 16; r++) {
                    int idx = r * 256 + t;
                    int j = idx >> 5, kk = idx & 31;
                    wr[r] = (j < 64)
                        ? Wfc1[j * 256 + (c + 1) * 32 + kk]
                        : Wfc1[(j - 64) * 256 + 128 + (c + 1) * 32 + kk];
                }
            }
            #pragma unroll
            for (int kk = 0; kk < 32; kk++) {
                unsigned long long wv0 = pack2(ws[j0 * 37 + kk]);
                unsigned long long wv1 = pack2(ws[(j0 + 64) * 37 + kk]);
                const ulonglong2* mr =
                    (const ulonglong2*)(mvs + (c * 32 + kk) * 36 + on);
                #pragma unroll
                for (int q = 0; q < 2; q++) {
                    ulonglong2 m2 = mr[q];
                    ffma2(aA[2*q],   wv0, m2.x);
                    ffma2(aA[2*q+1], wv0, m2.y);
                    ffma2(aB[2*q],   wv1, m2.x);
                    ffma2(aB[2*q+1], wv1, m2.y);
                }
            }
            __syncthreads();
        }

        // store A, B (+bias fold into B); exact tiling, no bounds checks
        #pragma unroll
        for (int q = 0; q < 4; q++) {
            float2 pa  = unpack2(aA[q]);
            float2 pb2 = unpack2(aB[q]);
            int n = n0 + on + 2 * q;
            g_A[(size_t)n * 64 + j0]       = pa.x;
            g_A[(size_t)(n + 1) * 64 + j0] = pa.y;
            g_B[(size_t)n * 64 + j0]       = pb2.x + bias;
            g_B[(size_t)(n + 1) * 64 + j0] = pb2.y + bias;
        }
    }
}

// =====================================================================
// Edge kernel: 8 threads/edge, difference-weight trick (R7/R12, ~61us,
// at its random-gather L2/issue roofline).
// =====================================================================
#define EPB 256
__global__ void __launch_bounds__(256) edge_kernel(
    const int*   __restrict__ ei,      // (2, 3*NE)
    const float* __restrict__ gum,     // (NE, 2)
    const float* __restrict__ Wfc2,    // (2, 64)
    const float* __restrict__ bfc2,    // (2,)
    float*       __restrict__ out)     // (3*NE,)
{
    __shared__ float sact[EPB];
    const int t  = threadIdx.x;
    const int g  = t & 7;
    const int gi = t >> 3;

    float wd[8];
    #pragma unroll
    for (int u = 0; u < 4; u++) {
        wd[u]     = Wfc2[g * 4 + u]      - Wfc2[64 + g * 4 + u];
        wd[4 + u] = Wfc2[32 + g * 4 + u] - Wfc2[96 + g * 4 + u];
    }
    const float cdiff = bfc2[0] - bfc2[1];
    const size_t e0 = (size_t)blockIdx.x * EPB;

    #pragma unroll
    for (int it = 0; it < EPB / 32; it++) {
        int    el = it * 32 + gi;
        size_t e  = e0 + el;

        int src = ei[e];
        int dst = ei[NE3 + e];
        const float4* ap = (const float4*)(g_A + (size_t)src * 64);
        const float4* bp = (const float4*)(g_B + (size_t)dst * 64);
        float4 a0 = ap[g], a1 = ap[8 + g];
        float4 b0 = bp[g], b1 = bp[8 + g];

        float sd = 0.0f, r;
        r = fmaxf(a0.x + b0.x, 0.f); sd = fmaf(wd[0], r, sd);
        r = fmaxf(a0.y + b0.y, 0.f); sd = fmaf(wd[1], r, sd);
        r = fmaxf(a0.z + b0.z, 0.f); sd = fmaf(wd[2], r, sd);
        r = fmaxf(a0.w + b0.w, 0.f); sd = fmaf(wd[3], r, sd);
        r = fmaxf(a1.x + b1.x, 0.f); sd = fmaf(wd[4], r, sd);
        r = fmaxf(a1.y + b1.y, 0.f); sd = fmaf(wd[5], r, sd);
        r = fmaxf(a1.z + b1.z, 0.f); sd = fmaf(wd[6], r, sd);
        r = fmaxf(a1.w + b1.w, 0.f); sd = fmaf(wd[7], r, sd);

        #pragma unroll
        for (int m = 1; m < 8; m <<= 1)
            sd += __shfl_xor_sync(0xffffffff, sd, m);

        if (g == 0) {
            float2 gm = ((const float2*)gum)[e];
            sact[el] = (sd + cdiff + gm.x - gm.y >= 0.0f) ? 1.0f : 0.0f;
        }
    }
    __syncthreads();

    float a = sact[t];
    out[e0 + t]          = a;
    out[NE + e0 + t]     = 1.0f - a;
    out[2 * NE + e0 + t] = 1.0f - a;
}

// =====================================================================
extern "C" void kernel_launch(void* const* d_in, const int* in_sizes, int n_in,
                              void* d_out, int out_size)
{
    const float* trace = (const float*)d_in[0];  // (2,100000,128)
    const float* Wlin  = (const float*)d_in[1];  // (256,256)
    const float* Wlin2 = (const float*)d_in[2];  // (128,256)
    const float* Wfc1  = (const float*)d_in[3];  // (64,256)
    const float* bfc1  = (const float*)d_in[4];  // (64,)
    const float* Wfc2  = (const float*)d_in[5];  // (2,64)
    const float* bfc2  = (const float*)d_in[6];  // (2,)
    const float* gum   = (const float*)d_in[7];  // (NE,2)
    const int*   ei    = (const int*)d_in[8];    // (2,3*NE)

    cudaFuncSetAttribute(node_kernel,
                         cudaFuncAttributeMaxDynamicSharedMemorySize, SMEM_BYTES);

    int nblocks = N_NODES / BN;              // 3125 exact
    node_kernel<<<nblocks, TPB, SMEM_BYTES>>>(trace, Wlin, Wlin2, Wfc1, bfc1);

    int eblocks = NE / EPB;                  // 6250
    edge_kernel<<<eblocks, 256>>>(ei, gum, Wfc2, bfc2, (float*)d_out);
}

// round 16
// speedup vs baseline: 1.2915x; 1.2915x over previous
#include <cuda_runtime.h>
#include <cuda_bf16.h>

// ---------------- problem constants ----------------
#define N_NODES 100000
#define NE      1600000
#define NE3     4800000

// per-node precomputed A = Wfc1[:, :128] @ mvc_norm, B = Wfc1[:, 128:] @ mvc_norm + b_fc1
__device__ __align__(16) float g_A[(size_t)N_NODES * 64];
__device__ __align__(16) float g_B[(size_t)N_NODES * 64];

// Wlin split into 3 bf16 planes, stored in m16n8k16 A-fragment-direct order:
// [s][c][mtile][lane][4] u32  (s=split, c=k-chunk of 16, mtile=16-row tile)
__device__ __align__(16) unsigned g_Wfrag[3 * 16 * 16 * 32 * 4];

#define BN  32      // nodes per block (100000 = 3125 * 32, exact)
#define TPB 256

// ---- shared memory layout (floats / u32) ----
// XS : 3 x [128 kp][40] u32 bf16x2 split-X; region reused for h [c][36] f32
// mvs: [128][36] f32
// ws : [row][37] f32 staged weights for GEMM2/3
constexpr int XS_OFF  = 0;
constexpr int XS_PL   = 128 * 40;            // 5120 per split plane
constexpr int XS_SZ   = 3 * XS_PL;           // 15360
constexpr int MV_OFF  = XS_OFF + XS_SZ;      // 15360
constexpr int MV_SZ   = 128 * 36;            // 4608
constexpr int WS_OFF  = MV_OFF + MV_SZ;      // 19968
constexpr int WS_SZ   = 128 * 37;            // 4736
constexpr int RED_OFF = WS_OFF + WS_SZ;      // 24704
constexpr int RED_SZ  = 8 * 32 + 32;         // 288
constexpr int SMEM_FLOATS = RED_OFF + RED_SZ;     // 24992
constexpr int SMEM_BYTES  = SMEM_FLOATS * 4;      // 99968 B -> 2 blocks/SM

// ---------------- packed fp32x2 helpers (sm_103a) ----------------
__device__ __forceinline__ unsigned long long pack2(float v) {
    unsigned long long r;
    asm("mov.b64 %0, {%1, %1};" : "=l"(r) : "f"(v));
    return r;
}
__device__ __forceinline__ void ffma2(unsigned long long& d,
                                      unsigned long long a,
                                      unsigned long long b) {
    asm("fma.rn.f32x2 %0, %1, %2, %0;" : "+l"(d) : "l"(a), "l"(b));
}
__device__ __forceinline__ float2 unpack2(unsigned long long v) {
    float2 f;
    asm("mov.b64 {%0, %1}, %2;" : "=f"(f.x), "=f"(f.y) : "l"(v));
    return f;
}

// ---------------- exact 3-way bf16 split ----------------
// x = b0 + b1 + b2 (8+8+8 mantissa bits; residual subtractions are
// Sterbenz-exact, leftover <= 2^-25 relative).
__device__ __forceinline__ void split3b(float x, unsigned short& s0,
                                        unsigned short& s1, unsigned short& s2) {
    __nv_bfloat16 b0 = __float2bfloat16(x);
    float r1 = x - __bfloat162float(b0);
    __nv_bfloat16 b1 = __float2bfloat16(r1);
    float r2 = r1 - __bfloat162float(b1);
    __nv_bfloat16 b2 = __float2bfloat16(r2);
    s0 = __bfloat16_as_ushort(b0);
    s1 = __bfloat16_as_ushort(b1);
    s2 = __bfloat16_as_ushort(b2);
}
__device__ __forceinline__ unsigned pack_bf(unsigned short lo, unsigned short hi) {
    return (unsigned)lo | ((unsigned)hi << 16);
}

// mma m16n8k16 bf16, fp32 accumulate: D += A*B
__device__ __forceinline__ void mma16(float* d, const unsigned* a, const unsigned* b) {
    asm("mma.sync.aligned.m16n8k16.row.col.f32.bf16.bf16.f32 "
        "{%0,%1,%2,%3}, {%4,%5,%6,%7}, {%8,%9}, {%0,%1,%2,%3};"
        : "+f"(d[0]), "+f"(d[1]), "+f"(d[2]), "+f"(d[3])
        : "r"(a[0]), "r"(a[1]), "r"(a[2]), "r"(a[3]), "r"(b[0]), "r"(b[1]));
}

// =====================================================================
// Setup kernel: split Wlin into 3 bf16 planes in A-fragment-direct
// layout. 24576 threads, runs in a few us.
//   A[m][k] = Wlin[m][k]; fragment regs for (c, mtile, lane):
//   j0: (row=16mt+qid,   k=16c+2tig,+1)  j1: (row+8, same k)
//   j2: (row=16mt+qid,   k=16c+2tig+8,+9) j3: (row+8, same k)
// =====================================================================
__global__ void split_wlin_kernel(const float* __restrict__ Wlin) {
    int tid = blockIdx.x * 256 + threadIdx.x;   // 0..24575
    if (tid >= 3 * 16 * 16 * 32) return;
    int lane = tid & 31;
    int mt   = (tid >> 5) & 15;
    int c    = (tid >> 9) & 15;
    int s    = tid >> 13;
    int qid = lane >> 2, tig = lane & 3;

    unsigned out[4];
    #pragma unroll
    for (int j = 0; j < 4; j++) {
        int row = 16 * mt + qid + ((j & 1) ? 8 : 0);
        int col = 16 * c + 2 * tig + ((j & 2) ? 8 : 0);
        float x0 = Wlin[row * 256 + col];
        float x1 = Wlin[row * 256 + col + 1];
        unsigned short a0, a1, a2, b0, b1, b2;
        split3b(x0, a0, a1, a2);
        split3b(x1, b0, b1, b2);
        unsigned short lo = (s == 0) ? a0 : (s == 1) ? a1 : a2;
        unsigned short hi = (s == 0) ? b0 : (s == 1) ? b1 : b2;
        out[j] = pack_bf(lo, hi);
    }
    *(uint4*)&g_Wfrag[(size_t)tid * 4] =
        make_uint4(out[0], out[1], out[2], out[3]);
}

// =====================================================================
// Node kernel: 32-node tile, 256 threads, 2 blocks/SM.
// GEMM1 on bf16 tensor cores (6-product exact-split emulation);
// GEMM2/3 scalar f32x2 (R12 math, bit-identical).
// =====================================================================
__global__ void __launch_bounds__(TPB, 2) node_kernel(
    const float* __restrict__ trace,   // (2, N, 128)
    const float* __restrict__ Wlin2,   // (128, 256)
    const float* __restrict__ Wfc1,    // (64, 256)
    const float* __restrict__ bfc1)    // (64,)
{
    extern __shared__ float sm[];
    unsigned* XSu = (unsigned*)sm;     // 3 planes of [kp][40]
    float* hs  = sm + XS_OFF;          // h [c][36] (reuses XS region)
    float* mvs = sm + MV_OFF;          // [c][36]
    float* ws  = sm + WS_OFF;          // [row][37]
    float* red = sm + RED_OFF;         // [8][32]
    float* nrm = red + 256;            // [32]

    const int t    = threadIdx.x;
    const int lane = t & 31;
    const int w    = t >> 5;     // 0..7
    const int qid  = lane >> 2;  // 0..7
    const int tig  = lane & 3;   // 0..3
    const int n0   = blockIdx.x * BN;

    // ---- load X, split into 3 bf16 planes (u32 bf16x2 k-pairs) ----
    #pragma unroll
    for (int i = 0; i < 4; i++) {
        int nl = w * 4 + i;
        int n  = n0 + nl;
        #pragma unroll
        for (int j = 0; j < 4; j++) {
            int kp = lane + 32 * j;   // 0..127
            float2 xp = (kp < 64)
                ? *(const float2*)(trace + (size_t)n * 128 + 2 * kp)
                : *(const float2*)(trace + (size_t)(N_NODES + n) * 128 + 2 * kp - 128);
            unsigned short a0, a1, a2, b0, b1, b2;
            split3b(xp.x, a0, a1, a2);
            split3b(xp.y, b0, b1, b2);
            XSu[0 * XS_PL + kp * 40 + nl] = pack_bf(a0, b0);
            XSu[1 * XS_PL + kp * 40 + nl] = pack_bf(a1, b1);
            XSu[2 * XS_PL + kp * 40 + nl] = pack_bf(a2, b2);
        }
    }
    __syncthreads();

    // ================= GEMM1 (tensor): h = relu(Wlin @ x) =================
    // M=256 (warp w owns m-tiles 2w,2w+1), N=32 (4 n8-tiles), K=256 (16 chunks).
    float dacc[2][4][4];
    #pragma unroll
    for (int a = 0; a < 2; a++)
        #pragma unroll
        for (int b = 0; b < 4; b++)
            #pragma unroll
            for (int cc = 0; cc < 4; cc++) dacc[a][b][cc] = 0.0f;

    unsigned Af[2][2][3][4];   // [parity][mt][s][reg]
    #pragma unroll
    for (int mt = 0; mt < 2; mt++)
        #pragma unroll
        for (int s = 0; s < 3; s++) {
            uint4 v = *(const uint4*)&g_Wfrag[
                ((size_t)((s * 16 + 0) * 16 + (2 * w + mt)) * 32 + lane) * 4];
            Af[0][mt][s][0] = v.x; Af[0][mt][s][1] = v.y;
            Af[0][mt][s][2] = v.z; Af[0][mt][s][3] = v.w;
        }

    for (int c = 0; c < 16; c++) {
        if (c < 15) {
            #pragma unroll
            for (int mt = 0; mt < 2; mt++)
                #pragma unroll
                for (int s = 0; s < 3; s++) {
                    uint4 v = *(const uint4*)&g_Wfrag[
                        ((size_t)((s * 16 + c + 1) * 16 + (2 * w + mt)) * 32 + lane) * 4];
                    Af[(c + 1) & 1][mt][s][0] = v.x;
                    Af[(c + 1) & 1][mt][s][1] = v.y;
                    Af[(c + 1) & 1][mt][s][2] = v.z;
                    Af[(c + 1) & 1][mt][s][3] = v.w;
                }
        }
        const unsigned (*A)[3][4] = Af[c & 1];
        const int kb = (8 * c + tig) * 40;
        #pragma unroll
        for (int nt = 0; nt < 4; nt++) {
            const int ba = kb + nt * 8 + qid;
            unsigned B0[2], B1[2], B2[2];
            B0[0] = XSu[ba];              B0[1] = XSu[ba + 160];
            B1[0] = XSu[XS_PL + ba];      B1[1] = XSu[XS_PL + ba + 160];
            B2[0] = XSu[2 * XS_PL + ba];  B2[1] = XSu[2 * XS_PL + ba + 160];
            #pragma unroll
            for (int mt = 0; mt < 2; mt++) {
                float* D = dacc[mt][nt];
                mma16(D, A[mt][0], B0);   // 0*0
                mma16(D, A[mt][0], B1);   // 0*1
                mma16(D, A[mt][1], B0);   // 1*0
                mma16(D, A[mt][1], B1);   // 1*1
                mma16(D, A[mt][0], B2);   // 0*2
                mma16(D, A[mt][2], B0);   // 2*0
            }
        }
    }
    __syncthreads();   // all XS reads done; region becomes h

    // ---- prefetch GEMM2 chunk 0 (16 floats/thread) ----
    float wr[16];
    #pragma unroll
    for (int r = 0; r < 16; r++) {
        int idx = r * 256 + t;
        wr[r] = Wlin2[(idx >> 5) * 256 + (idx & 31)];
    }

    // ---- store h = relu(D) into hs [c][36] ----
    #pragma unroll
    for (int mt = 0; mt < 2; mt++) {
        int cb = 32 * w + 16 * mt;
        #pragma unroll
        for (int nt = 0; nt < 4; nt++) {
            float* D = dacc[mt][nt];
            int ncol = nt * 8 + 2 * tig;
            *(float2*)(hs + (cb + qid) * 36 + ncol) =
                make_float2(fmaxf(D[0], 0.f), fmaxf(D[1], 0.f));
            *(float2*)(hs + (cb + 8 + qid) * 36 + ncol) =
                make_float2(fmaxf(D[2], 0.f), fmaxf(D[3], 0.f));
        }
    }

    // ================= GEMM2 (scalar f32x2): mvc = Wlin2 @ h =================
    const int d0 = t & 63;
    const int on = (t >> 6) * 8;
    {
        unsigned long long c0a[4], c1a[4];
        #pragma unroll
        for (int i = 0; i < 4; i++) { c0a[i] = 0ull; c1a[i] = 0ull; }

        for (int c = 0; c < 8; c++) {
            #pragma unroll
            for (int r = 0; r < 16; r++) {
                int idx = r * 256 + t;
                ws[(idx >> 5) * 37 + (idx & 31)] = wr[r];
            }
            __syncthreads();   // c==0: publishes h stores + ws chunk 0
            if (c < 7) {
                #pragma unroll
                for (int r = 0; r < 16; r++) {
                    int idx = r * 256 + t;
                    wr[r] = Wlin2[(idx >> 5) * 256 + (c + 1) * 32 + (idx & 31)];
                }
            }
            #pragma unroll
            for (int kk = 0; kk < 32; kk++) {
                unsigned long long wv0 = pack2(ws[d0 * 37 + kk]);
                unsigned long long wv1 = pack2(ws[(d0 + 64) * 37 + kk]);
                const ulonglong2* hr =
                    (const ulonglong2*)(hs + (c * 32 + kk) * 36 + on);
                #pragma unroll
                for (int q = 0; q < 2; q++) {
                    ulonglong2 h2 = hr[q];
                    ffma2(c0a[2*q],   wv0, h2.x);
                    ffma2(c0a[2*q+1], wv0, h2.y);
                    ffma2(c1a[2*q],   wv1, h2.x);
                    ffma2(c1a[2*q+1], wv1, h2.y);
                }
            }
            __syncthreads();
        }
        // store mvc (disjoint region)
        float4* m0 = (float4*)(mvs + d0 * 36 + on);
        float4* m1 = (float4*)(mvs + (d0 + 64) * 36 + on);
        #pragma unroll
        for (int q = 0; q < 2; q++) {
            float2 p = unpack2(c0a[2*q]), r2 = unpack2(c0a[2*q+1]);
            m0[q] = make_float4(p.x, p.y, r2.x, r2.y);
            p = unpack2(c1a[2*q]); r2 = unpack2(c1a[2*q+1]);
            m1[q] = make_float4(p.x, p.y, r2.x, r2.y);
        }
    }
    __syncthreads();   // mvs stores visible

    // ---- prefetch GEMM3 chunk 0 (combined [A;B] rows) ----
    #pragma unroll
    for (int r = 0; r < 16; r++) {
        int idx = r * 256 + t;
        int j = idx >> 5, kk = idx & 31;
        wr[r] = (j < 64) ? Wfc1[j * 256 + kk]
                         : Wfc1[(j - 64) * 256 + 128 + kk];
    }
    const float bias = __ldg(&bfc1[t & 63]);

    // ---------------- row norm + normalize ----------------
    {
        int n = t & 31, p = t >> 5;   // 8 groups x 16 cols
        float s = 0.0f;
        #pragma unroll 4
        for (int cc = p * 16; cc < p * 16 + 16; cc++) {
            float v = mvs[cc * 36 + n];
            s += v * v;
        }
        red[p * 32 + n] = s;
        __syncthreads();
        if (t < 32) {
            float ss = 0.0f;
            #pragma unroll
            for (int p2 = 0; p2 < 8; p2++) ss += red[p2 * 32 + t];
            nrm[t] = fmaxf(sqrtf(ss), 1e-12f);
        }
        __syncthreads();
        #pragma unroll
        for (int i = 0; i < 16; i++) {
            int idx = i * TPB + t;
            int cc = idx >> 5, n2 = idx & 31;
            mvs[cc * 36 + n2] = mvs[cc * 36 + n2] / nrm[n2];
        }
    }

    // ================= GEMM3 (scalar f32x2): A/B = Wfc1-split @ mvc_norm =================
    {
        const int j0 = t & 63;
        unsigned long long aA[4], aB[4];
        #pragma unroll
        for (int i = 0; i < 4; i++) { aA[i] = 0ull; aB[i] = 0ull; }

        for (int c = 0; c < 4; c++) {
            #pragma unroll
            for (int r = 0; r < 16; r++) {
                int idx = r * 256 + t;
                ws[(idx >> 5) * 37 + (idx & 31)] = wr[r];
            }
            __syncthreads();   // c==0: publishes normalized mvs + ws chunk 0
            if (c < 3) {
                #pragma unroll
                for (int r = 0; r < 16; r++) {
                    int idx = r * 256 + t;
                    int j = idx >> 5, kk = idx & 31;
                    wr[r] = (j < 64)
                        ? Wfc1[j * 256 + (c + 1) * 32 + kk]
                        : Wfc1[(j - 64) * 256 + 128 + (c + 1) * 32 + kk];
                }
            }
            #pragma unroll
            for (int kk = 0; kk < 32; kk++) {
                unsigned long long wv0 = pack2(ws[j0 * 37 + kk]);
                unsigned long long wv1 = pack2(ws[(j0 + 64) * 37 + kk]);
                const ulonglong2* mr =
                    (const ulonglong2*)(mvs + (c * 32 + kk) * 36 + on);
                #pragma unroll
                for (int q = 0; q < 2; q++) {
                    ulonglong2 m2 = mr[q];
                    ffma2(aA[2*q],   wv0, m2.x);
                    ffma2(aA[2*q+1], wv0, m2.y);
                    ffma2(aB[2*q],   wv1, m2.x);
                    ffma2(aB[2*q+1], wv1, m2.y);
                }
            }
            __syncthreads();
        }

        // store A, B (+bias fold into B); exact tiling
        #pragma unroll
        for (int q = 0; q < 4; q++) {
            float2 pa  = unpack2(aA[q]);
            float2 pb2 = unpack2(aB[q]);
            int n = n0 + on + 2 * q;
            g_A[(size_t)n * 64 + j0]       = pa.x;
            g_A[(size_t)(n + 1) * 64 + j0] = pa.y;
            g_B[(size_t)n * 64 + j0]       = pb2.x + bias;
            g_B[(size_t)(n + 1) * 64 + j0] = pb2.y + bias;
        }
    }
}

// =====================================================================
// Edge kernel: 8 threads/edge, difference-weight trick (R7/R12, ~61us,
// at its random-gather L2/issue roofline).
// =====================================================================
#define EPB 256
__global__ void __launch_bounds__(256) edge_kernel(
    const int*   __restrict__ ei,      // (2, 3*NE)
    const float* __restrict__ gum,     // (NE, 2)
    const float* __restrict__ Wfc2,    // (2, 64)
    const float* __restrict__ bfc2,    // (2,)
    float*       __restrict__ out)     // (3*NE,)
{
    __shared__ float sact[EPB];
    const int t  = threadIdx.x;
    const int g  = t & 7;
    const int gi = t >> 3;

    float wd[8];
    #pragma unroll
    for (int u = 0; u < 4; u++) {
        wd[u]     = Wfc2[g * 4 + u]      - Wfc2[64 + g * 4 + u];
        wd[4 + u] = Wfc2[32 + g * 4 + u] - Wfc2[96 + g * 4 + u];
    }
    const float cdiff = bfc2[0] - bfc2[1];
    const size_t e0 = (size_t)blockIdx.x * EPB;

    #pragma unroll
    for (int it = 0; it < EPB / 32; it++) {
        int    el = it * 32 + gi;
        size_t e  = e0 + el;

        int src = ei[e];
        int dst = ei[NE3 + e];
        const float4* ap = (const float4*)(g_A + (size_t)src * 64);
        const float4* bp = (const float4*)(g_B + (size_t)dst * 64);
        float4 a0 = ap[g], a1 = ap[8 + g];
        float4 b0 = bp[g], b1 = bp[8 + g];

        float sd = 0.0f, r;
        r = fmaxf(a0.x + b0.x, 0.f); sd = fmaf(wd[0], r, sd);
        r = fmaxf(a0.y + b0.y, 0.f); sd = fmaf(wd[1], r, sd);
        r = fmaxf(a0.z + b0.z, 0.f); sd = fmaf(wd[2], r, sd);
        r = fmaxf(a0.w + b0.w, 0.f); sd = fmaf(wd[3], r, sd);
        r = fmaxf(a1.x + b1.x, 0.f); sd = fmaf(wd[4], r, sd);
        r = fmaxf(a1.y + b1.y, 0.f); sd = fmaf(wd[5], r, sd);
        r = fmaxf(a1.z + b1.z, 0.f); sd = fmaf(wd[6], r, sd);
        r = fmaxf(a1.w + b1.w, 0.f); sd = fmaf(wd[7], r, sd);

        #pragma unroll
        for (int m = 1; m < 8; m <<= 1)
            sd += __shfl_xor_sync(0xffffffff, sd, m);

        if (g == 0) {
            float2 gm = ((const float2*)gum)[e];
            sact[el] = (sd + cdiff + gm.x - gm.y >= 0.0f) ? 1.0f : 0.0f;
        }
    }
    __syncthreads();

    float a = sact[t];
    out[e0 + t]          = a;
    out[NE + e0 + t]     = 1.0f - a;
    out[2 * NE + e0 + t] = 1.0f - a;
}

// =====================================================================
extern "C" void kernel_launch(void* const* d_in, const int* in_sizes, int n_in,
                              void* d_out, int out_size)
{
    const float* trace = (const float*)d_in[0];  // (2,100000,128)
    const float* Wlin  = (const float*)d_in[1];  // (256,256)
    const float* Wlin2 = (const float*)d_in[2];  // (128,256)
    const float* Wfc1  = (const float*)d_in[3];  // (64,256)
    const float* bfc1  = (const float*)d_in[4];  // (64,)
    const float* Wfc2  = (const float*)d_in[5];  // (2,64)
    const float* bfc2  = (const float*)d_in[6];  // (2,)
    const float* gum   = (const float*)d_in[7];  // (NE,2)
    const int*   ei    = (const int*)d_in[8];    // (2,3*NE)

    cudaFuncSetAttribute(node_kernel,
                         cudaFuncAttributeMaxDynamicSharedMemorySize, SMEM_BYTES);

    split_wlin_kernel<<<96, 256>>>(Wlin);        // 24576 threads, ~few us

    int nblocks = N_NODES / BN;              // 3125 exact
    node_kernel<<<nblocks, TPB, SMEM_BYTES>>>(trace, Wlin2, Wfc1, bfc1);

    int eblocks = NE / EPB;                  // 6250
    edge_kernel<<<eblocks, 256>>>(ei, gum, Wfc2, bfc2, (float*)d_out);
}